// round 7
// baseline (speedup 1.0000x reference)
#include <cuda_runtime.h>
#include <cstdint>

#define Bb 2
#define Nn 2048
#define Cc 384
#define Hh 6
#define Dd 64
#define BN 4096
#define C3 1152
#define BHh 12
#define SROW 2064   // padded smem row stride (bytes), mult of 16

#define PHYS32(v) (((v) & ~31) | (((v) & 12) << 1) | (((v) & 16) >> 2) | ((v) & 3))

// ---- scratch (device globals; no runtime allocation) ----
__device__ int8_t g_xq[BN * Cc];
__device__ int8_t g_wqkv[C3 * Cc];
__device__ int8_t g_wproj[Cc * Cc];
__device__ int8_t g_q[BHh * Nn * Dd];    // [b,h,n,phys(d)]
__device__ int8_t g_k[BHh * Nn * Dd];    // [b,h,n,phys(d)]
__device__ int8_t g_vT[BHh * Dd * Nn];   // [b,h,d,phys(n)]
__device__ int8_t g_o[BN * Cc];          // [b,n, phys(h*64+d)], alpha = a_proj_a

__device__ __forceinline__ int q8i(float v) {
    return __float2int_rn(fminf(fmaxf(v, -128.f), 127.f));
}

__device__ __forceinline__ void mma8(int* c, const unsigned* a, const unsigned* b) {
    asm volatile(
        "mma.sync.aligned.m16n8k32.row.col.s32.s8.s8.s32 "
        "{%0,%1,%2,%3}, {%4,%5,%6,%7}, {%8,%9}, {%0,%1,%2,%3};\n"
        : "+r"(c[0]), "+r"(c[1]), "+r"(c[2]), "+r"(c[3])
        : "r"(a[0]), "r"(a[1]), "r"(a[2]), "r"(a[3]), "r"(b[0]), "r"(b[1]));
}

// ---------------- merged quantize kernel (writes perm layout) ----------------
__global__ void quant_all_k(const float* __restrict__ x,
                            const float* __restrict__ wqkv,
                            const float* __restrict__ wproj,
                            const float* __restrict__ a_a,
                            const float* __restrict__ a_w,
                            const float* __restrict__ a_pw) {
    int b = blockIdx.x;
    const float* src;
    int8_t* dst;
    const float* al;
    int i;
    if (b < 1536)      { src = x;     dst = g_xq;    al = a_a;  i = b * 256 + threadIdx.x; }
    else if (b < 1968) { src = wqkv;  dst = g_wqkv;  al = a_w;  i = (b - 1536) * 256 + threadIdx.x; }
    else               { src = wproj; dst = g_wproj; al = a_pw; i = (b - 1968) * 256 + threadIdx.x; }
    float ia = 1.f / __ldg(al);
    float4 v = ((const float4*)src)[i];
    char4 r;
    r.x = (char)q8i(v.x * ia); r.y = (char)q8i(v.y * ia);
    r.z = (char)q8i(v.z * ia); r.w = (char)q8i(v.w * ia);
    int c4 = (i * 4) % Cc;
    int row = (i * 4) / Cc;
    int pc = (c4 & ~31) + (((c4 >> 2) & 3) << 3) + (((c4 >> 4) & 1) << 2);
    *(char4*)(dst + row * Cc + pc) = r;
}

// ---------------- GEMM1: qkv = xq @ wqkv^T, requant-split into q/k/vT ----------------
__global__ void __launch_bounds__(256) gemm_qkv_k(
    const float* al_a, const float* al_w,
    const float* al_q, const float* al_k, const float* al_v) {
    const int bm = blockIdx.y * 128;
    const int bn = blockIdx.x * 128;
    const int wid = threadIdx.x >> 5;
    const int lane = threadIdx.x & 31;
    const int wm = (wid & 3) * 32;
    const int wn = (wid >> 2) * 64;
    const int lr = lane >> 2;
    const int q8 = (lane & 3) << 3;

    int c[2][8][4];
#pragma unroll
    for (int i = 0; i < 2; i++)
#pragma unroll
        for (int j = 0; j < 8; j++)
#pragma unroll
            for (int t = 0; t < 4; t++) c[i][j][t] = 0;

#pragma unroll 2
    for (int k0 = 0; k0 < Cc; k0 += 32) {
        unsigned a[2][4];
#pragma unroll
        for (int mt = 0; mt < 2; mt++) {
            const int8_t* ap = g_xq + (bm + wm + mt * 16 + lr) * Cc + k0 + q8;
            uint2 lo = *(const uint2*)ap;
            uint2 hi = *(const uint2*)(ap + 8 * Cc);
            a[mt][0] = lo.x; a[mt][2] = lo.y;
            a[mt][1] = hi.x; a[mt][3] = hi.y;
        }
#pragma unroll
        for (int nt = 0; nt < 8; nt++) {
            uint2 bv = *(const uint2*)(g_wqkv + (bn + wn + nt * 8 + lr) * Cc + k0 + q8);
            unsigned bb[2] = {bv.x, bv.y};
            mma8(c[0][nt], a[0], bb);
            mma8(c[1][nt], a[1], bb);
        }
    }

    const float c1 = __ldg(al_a) * __ldg(al_w);
    const float iq = c1 / __ldg(al_q), ik = c1 / __ldg(al_k), iv = c1 / __ldg(al_v);
#pragma unroll
    for (int mt = 0; mt < 2; mt++)
#pragma unroll
        for (int nt = 0; nt < 8; nt++)
#pragma unroll
            for (int j = 0; j < 4; j++) {
                int row = bm + wm + mt * 16 + lr + ((j >> 1) << 3);
                int col = bn + wn + nt * 8 + ((lane & 3) << 1) + (j & 1);
                float f = (float)c[mt][nt][j];
                int b = row >> 11, n = row & (Nn - 1);
                int which = col / Cc;
                int cr = col - which * Cc;
                int h = cr >> 6, d = cr & 63;
                if (which == 0)
                    g_q[((b * Hh + h) * Nn + n) * Dd + PHYS32(d)] = (int8_t)q8i(f * iq);
                else if (which == 1)
                    g_k[((b * Hh + h) * Nn + n) * Dd + PHYS32(d)] = (int8_t)q8i(f * ik);
                else
                    g_vT[((b * Hh + h) * Dd + d) * Nn + PHYS32(n)] = (int8_t)q8i(f * iv);
            }
}

// ---------------- fused attention: 128 threads, 3 CTAs/SM for phase overlap ----
#define LUTF_OFF (32 * SROW)           // 66048: float[256] exp LUT
#define LUT8_OFF (LUTF_OFF + 1024)     // 67072: per-warp int8 requant LUT (4*256)
#define SUMS_OFF (LUT8_OFF + 1024)     // 68096: float[4][32] per-warp row partials
#define INVR_OFF (SUMS_OFF + 512)      // 68608: float[32] per-row inv
#define SMEM_SZ  (INVR_OFF + 128)      // 68736  (x3 CTAs = 206KB <= 228KB)

__global__ void __launch_bounds__(128, 3) attn_fused_k(
    const float* al_q, const float* al_k, const float* al_attn, const float* al_attn2,
    const float* al_v, const float* al_pa) {
    extern __shared__ int8_t s_s[];  // [32][SROW] scores/probs + LUTs + sums
    const int bh = blockIdx.y;
    const int rb = blockIdx.x * 32;
    const int8_t* qp = g_q + bh * Nn * Dd;
    const int8_t* kp = g_k + bh * Nn * Dd;
    const int tid = threadIdx.x;
    const int wid = tid >> 5;
    const int lane = tid & 31;
    const int lr = lane >> 2;
    const int q8 = (lane & 3) << 3;
    const float aAttn = __ldg(al_attn);
    const float c2i = __ldg(al_q) * __ldg(al_k) * 0.125f / aAttn;
    const float a2 = __ldg(al_attn2);

    // build float exp LUT: lutf[u] = exp2(k2 * (signed char)u)
    float* lutf = (float*)(s_s + LUTF_OFF);
    {
        const float k2 = aAttn * 1.44269504f;
        lutf[tid] = exp2f(k2 * (float)(char)tid);
        lutf[tid + 128] = exp2f(k2 * (float)(char)(tid + 128));
    }

    // preload q fragments for the 32 rows (2 m-tiles), K=64 (2 k-steps)
    unsigned a[2][2][4];
#pragma unroll
    for (int mt = 0; mt < 2; mt++)
#pragma unroll
        for (int ks = 0; ks < 2; ks++) {
            const int8_t* ap = qp + (rb + mt * 16 + lr) * Dd + ks * 32 + q8;
            uint2 lo = *(const uint2*)ap;
            uint2 hi = *(const uint2*)(ap + 8 * Dd);
            a[mt][ks][0] = lo.x; a[mt][ks][2] = lo.y;
            a[mt][ks][1] = hi.x; a[mt][ks][3] = hi.y;
        }
    __syncthreads();   // lutf ready before Phase A uses it

    // ---- Phase A: QK^T over a 512-col stripe per warp, quant + fused exp row-sums ----
    float rsum[4] = {0.f, 0.f, 0.f, 0.f};  // rows: lr, lr+8, 16+lr, 24+lr
    const int nbase = wid * 512;
#pragma unroll 1
    for (int nc = 0; nc < 512; nc += 32) {
        int c[2][4][4];
#pragma unroll
        for (int i = 0; i < 2; i++)
#pragma unroll
            for (int j = 0; j < 4; j++)
#pragma unroll
                for (int t = 0; t < 4; t++) c[i][j][t] = 0;

#pragma unroll
        for (int nt = 0; nt < 4; nt++)
#pragma unroll
            for (int ks = 0; ks < 2; ks++) {
                uint2 bv = *(const uint2*)(kp + (nbase + nc + nt * 8 + lr) * Dd + ks * 32 + q8);
                unsigned bb[2] = {bv.x, bv.y};
                mma8(c[0][nt], a[0][ks], bb);
                mma8(c[1][nt], a[1][ks], bb);
            }
#pragma unroll
        for (int mt = 0; mt < 2; mt++)
#pragma unroll
            for (int nt = 0; nt < 4; nt++)
#pragma unroll
                for (int jj = 0; jj < 2; jj++) {
                    int row = mt * 16 + lr + jj * 8;
                    int col = nbase + nc + nt * 8 + ((lane & 3) << 1);
                    int pc = PHYS32(col);
                    int v0 = q8i((float)c[mt][nt][jj * 2 + 0] * c2i);
                    int v1 = q8i((float)c[mt][nt][jj * 2 + 1] * c2i);
                    rsum[mt * 2 + jj] += lutf[v0 & 255] + lutf[v1 & 255];
                    char2 o;
                    o.x = (char)v0; o.y = (char)v1;
                    *(char2*)(s_s + row * SROW + pc) = o;
                }
    }
#pragma unroll
    for (int i = 0; i < 4; i++) {
        rsum[i] += __shfl_xor_sync(0xffffffffu, rsum[i], 1);
        rsum[i] += __shfl_xor_sync(0xffffffffu, rsum[i], 2);
    }
    if ((lane & 3) == 0) {
        float* sm = (float*)(s_s + SUMS_OFF) + wid * 32;
        sm[lr] = rsum[0]; sm[lr + 8] = rsum[1];
        sm[lr + 16] = rsum[2]; sm[lr + 24] = rsum[3];
    }
    __syncthreads();
    if (tid < 32) {
        const float* sm = (float*)(s_s + SUMS_OFF);
        float t = sm[tid] + sm[32 + tid] + sm[64 + tid] + sm[96 + tid];
        ((float*)(s_s + INVR_OFF))[tid] = 1.f / (t * a2);
    }
    __syncthreads();

    // ---- Phase B: per-row requant via per-warp int8 LUT (8 rows/warp) ----
    {
        int8_t* lut8w = s_s + LUT8_OFF + wid * 256;
        const float* invr = (const float*)(s_s + INVR_OFF);
#pragma unroll 1
        for (int r = wid * 8; r < wid * 8 + 8; r++) {
            int8_t* srow = s_s + r * SROW;
            const float inv = invr[r];
            unsigned lo = 0, hi = 0;
#pragma unroll
            for (int j = 0; j < 8; j++) {
                int m = __float2int_rn(fminf(lutf[lane * 8 + j] * inv, 127.f));
                if (j < 4) lo |= (unsigned)(m & 255) << (8 * j);
                else       hi |= (unsigned)(m & 255) << (8 * (j - 4));
            }
            *(uint2*)(lut8w + lane * 8) = make_uint2(lo, hi);
            __syncwarp();
#pragma unroll
            for (int it = 0; it < 16; it++) {
                int8_t* p = srow + lane * 4 + it * 128;
                unsigned w = *(const unsigned*)p;
                unsigned r0 = (unsigned char)lut8w[w & 255];
                unsigned r1 = (unsigned char)lut8w[(w >> 8) & 255];
                unsigned r2 = (unsigned char)lut8w[(w >> 16) & 255];
                unsigned r3 = (unsigned char)lut8w[w >> 24];
                *(unsigned*)p = r0 | (r1 << 8) | (r2 << 16) | (r3 << 24);
            }
            __syncwarp();
        }
    }
    __syncthreads();

    // ---- Phase C: out = P @ V; each warp computes 16 rows x 32 cols ----
    {
        const int8_t* Vt = g_vT + bh * Dd * Nn;
        const int wm2 = (wid & 1) * 16;
        const int wn2 = (wid >> 1) * 32;
        int c[4][4];
#pragma unroll
        for (int i = 0; i < 4; i++)
#pragma unroll
            for (int t = 0; t < 4; t++) c[i][t] = 0;

#pragma unroll 2
        for (int k0 = 0; k0 < Nn; k0 += 32) {
            unsigned af[4];
            const int8_t* ap = s_s + (wm2 + lr) * SROW + k0 + q8;
            uint2 lo = *(const uint2*)ap;
            uint2 hi = *(const uint2*)(ap + 8 * SROW);
            af[0] = lo.x; af[2] = lo.y;
            af[1] = hi.x; af[3] = hi.y;
#pragma unroll
            for (int nt = 0; nt < 4; nt++) {
                uint2 bv = *(const uint2*)(Vt + (wn2 + nt * 8 + lr) * Nn + k0 + q8);
                unsigned bb[2] = {bv.x, bv.y};
                mma8(c[nt], af, bb);
            }
        }

        const float c3 = __ldg(al_attn2) * __ldg(al_v);
        const float ipa = c3 / __ldg(al_pa);
        const int b = bh / Hh, h = bh % Hh;
#pragma unroll
        for (int nt = 0; nt < 4; nt++)
#pragma unroll
            for (int j = 0; j < 4; j++) {
                int n = rb + wm2 + lr + ((j >> 1) << 3);
                int d = wn2 + nt * 8 + ((lane & 3) << 1) + (j & 1);
                g_o[(b * Nn + n) * Cc + h * Dd + PHYS32(d)] =
                    (int8_t)q8i((float)c[nt][j] * ipa);
            }
    }
}

// ---------------- GEMM2: 64x128 tile (grid 192) final projection + bias ----------------
__global__ void __launch_bounds__(256) gemm_proj_k(
    float* __restrict__ out, const float* __restrict__ bias,
    const float* al_pa, const float* al_pw) {
    const int bm = blockIdx.y * 64;
    const int bn = blockIdx.x * 128;
    const int wid = threadIdx.x >> 5;
    const int lane = threadIdx.x & 31;
    const int wm = (wid & 3) * 16;
    const int wn = (wid >> 2) * 64;
    const int lr = lane >> 2;
    const int q8 = (lane & 3) << 3;

    int c[8][4];
#pragma unroll
    for (int j = 0; j < 8; j++)
#pragma unroll
        for (int t = 0; t < 4; t++) c[j][t] = 0;

#pragma unroll 3
    for (int k0 = 0; k0 < Cc; k0 += 32) {
        unsigned a[4];
        {
            const int8_t* ap = g_o + (bm + wm + lr) * Cc + k0 + q8;
            uint2 lo = *(const uint2*)ap;
            uint2 hi = *(const uint2*)(ap + 8 * Cc);
            a[0] = lo.x; a[2] = lo.y;
            a[1] = hi.x; a[3] = hi.y;
        }
#pragma unroll
        for (int nt = 0; nt < 8; nt++) {
            uint2 bv = *(const uint2*)(g_wproj + (bn + wn + nt * 8 + lr) * Cc + k0 + q8);
            unsigned bb[2] = {bv.x, bv.y};
            mma8(c[nt], a, bb);
        }
    }

    const float sc = __ldg(al_pa) * __ldg(al_pw);
#pragma unroll
    for (int nt = 0; nt < 8; nt++)
#pragma unroll
        for (int j = 0; j < 4; j++) {
            int row = bm + wm + lr + ((j >> 1) << 3);
            int col = bn + wn + nt * 8 + ((lane & 3) << 1) + (j & 1);
            out[row * Cc + col] = (float)c[nt][j] * sc + __ldg(bias + col);
        }
}

extern "C" void kernel_launch(void* const* d_in, const int* in_sizes, int n_in,
                              void* d_out, int out_size) {
    const float* x        = (const float*)d_in[0];
    const float* w_qkv    = (const float*)d_in[1];
    const float* w_proj   = (const float*)d_in[2];
    const float* b_proj   = (const float*)d_in[3];
    const float* a_qkv_w  = (const float*)d_in[4];
    const float* a_qkv_a  = (const float*)d_in[5];
    const float* a_proj_w = (const float*)d_in[6];
    const float* a_proj_a = (const float*)d_in[7];
    const float* a_q      = (const float*)d_in[8];
    const float* a_k      = (const float*)d_in[9];
    const float* a_v      = (const float*)d_in[10];
    const float* a_attn   = (const float*)d_in[11];
    const float* a_attn2  = (const float*)d_in[12];
    float* out = (float*)d_out;

    quant_all_k<<<2112, 256>>>(x, w_qkv, w_proj, a_qkv_a, a_qkv_w, a_proj_w);

    gemm_qkv_k<<<dim3(C3 / 128, BN / 128), 256>>>(a_qkv_a, a_qkv_w, a_q, a_k, a_v);

    cudaFuncSetAttribute(attn_fused_k, cudaFuncAttributeMaxDynamicSharedMemorySize, SMEM_SZ);
    attn_fused_k<<<dim3(Nn / 32, BHh), 128, SMEM_SZ>>>(a_q, a_k, a_attn, a_attn2, a_v, a_proj_a);

    gemm_proj_k<<<dim3(Cc / 128, BN / 64), 256>>>(out, b_proj, a_proj_a, a_proj_w);
}

// round 8
// speedup vs baseline: 1.0379x; 1.0379x over previous
#include <cuda_runtime.h>
#include <cstdint>

#define Bb 2
#define Nn 2048
#define Cc 384
#define Hh 6
#define Dd 64
#define BN 4096
#define C3 1152
#define BHh 12
#define SROW 2064   // padded smem row stride (bytes), mult of 16

#define PHYS32(v) (((v) & ~31) | (((v) & 12) << 1) | (((v) & 16) >> 2) | ((v) & 3))

// ---- scratch (device globals; no runtime allocation) ----
__device__ int8_t g_xq[BN * Cc];
__device__ int8_t g_wqkv[C3 * Cc];
__device__ int8_t g_wproj[Cc * Cc];
__device__ int8_t g_q[BHh * Nn * Dd];    // [b,h,n,phys(d)]
__device__ int8_t g_k[BHh * Nn * Dd];    // [b,h,n,phys(d)]
__device__ int8_t g_vT[BHh * Dd * Nn];   // [b,h,d,phys(n)]
__device__ int8_t g_o[BN * Cc];          // [b,n, phys(h*64+d)], alpha = a_proj_a

__device__ __forceinline__ int q8i(float v) {
    return __float2int_rn(fminf(fmaxf(v, -128.f), 127.f));
}

__device__ __forceinline__ void mma8(int* c, const unsigned* a, const unsigned* b) {
    asm volatile(
        "mma.sync.aligned.m16n8k32.row.col.s32.s8.s8.s32 "
        "{%0,%1,%2,%3}, {%4,%5,%6,%7}, {%8,%9}, {%0,%1,%2,%3};\n"
        : "+r"(c[0]), "+r"(c[1]), "+r"(c[2]), "+r"(c[3])
        : "r"(a[0]), "r"(a[1]), "r"(a[2]), "r"(a[3]), "r"(b[0]), "r"(b[1]));
}

// ---------------- merged quantize kernel (writes perm layout) ----------------
__global__ void quant_all_k(const float* __restrict__ x,
                            const float* __restrict__ wqkv,
                            const float* __restrict__ wproj,
                            const float* __restrict__ a_a,
                            const float* __restrict__ a_w,
                            const float* __restrict__ a_pw) {
    int b = blockIdx.x;
    const float* src;
    int8_t* dst;
    const float* al;
    int i;
    if (b < 1536)      { src = x;     dst = g_xq;    al = a_a;  i = b * 256 + threadIdx.x; }
    else if (b < 1968) { src = wqkv;  dst = g_wqkv;  al = a_w;  i = (b - 1536) * 256 + threadIdx.x; }
    else               { src = wproj; dst = g_wproj; al = a_pw; i = (b - 1968) * 256 + threadIdx.x; }
    float ia = 1.f / __ldg(al);
    float4 v = ((const float4*)src)[i];
    char4 r;
    r.x = (char)q8i(v.x * ia); r.y = (char)q8i(v.y * ia);
    r.z = (char)q8i(v.z * ia); r.w = (char)q8i(v.w * ia);
    int c4 = (i * 4) % Cc;
    int row = (i * 4) / Cc;
    int pc = (c4 & ~31) + (((c4 >> 2) & 3) << 3) + (((c4 >> 4) & 1) << 2);
    *(char4*)(dst + row * Cc + pc) = r;
}

// ---- fragment loaders (row-major int8, perm layout, one LDG.64 per fragment pair) ----
__device__ __forceinline__ void ldA2(unsigned a[2][4], const int8_t* base, int k0,
                                     int stride) {
#pragma unroll
    for (int mt = 0; mt < 2; mt++) {
        const int8_t* ap = base + mt * 16 * stride + k0;
        uint2 lo = *(const uint2*)ap;
        uint2 hi = *(const uint2*)(ap + 8 * stride);
        a[mt][0] = lo.x; a[mt][2] = lo.y;
        a[mt][1] = hi.x; a[mt][3] = hi.y;
    }
}
__device__ __forceinline__ void ldB8(unsigned b[8][2], const int8_t* base, int k0,
                                     int stride) {
#pragma unroll
    for (int nt = 0; nt < 8; nt++) {
        uint2 bv = *(const uint2*)(base + nt * 8 * stride + k0);
        b[nt][0] = bv.x; b[nt][1] = bv.y;
    }
}

// ---------------- GEMM1: qkv = xq @ wqkv^T, requant-split (A/B double-buffered) ----
__global__ void __launch_bounds__(256) gemm_qkv_k(
    const float* al_a, const float* al_w,
    const float* al_q, const float* al_k, const float* al_v) {
    const int bm = blockIdx.y * 128;
    const int bn = blockIdx.x * 128;
    const int wid = threadIdx.x >> 5;
    const int lane = threadIdx.x & 31;
    const int wm = (wid & 3) * 32;
    const int wn = (wid >> 2) * 64;
    const int lr = lane >> 2;
    const int q8 = (lane & 3) << 3;
    const int8_t* abase = g_xq + (bm + wm + lr) * Cc + q8;
    const int8_t* bbase = g_wqkv + (bn + wn + lr) * Cc + q8;

    int c[2][8][4];
#pragma unroll
    for (int i = 0; i < 2; i++)
#pragma unroll
        for (int j = 0; j < 8; j++)
#pragma unroll
            for (int t = 0; t < 4; t++) c[i][j][t] = 0;

    unsigned A0[2][4], A1[2][4], B0[8][2], B1[8][2];
    ldA2(A0, abase, 0, Cc);
    ldB8(B0, bbase, 0, Cc);
#pragma unroll 1
    for (int k0 = 0; k0 < Cc; k0 += 64) {
        ldA2(A1, abase, k0 + 32, Cc);
        ldB8(B1, bbase, k0 + 32, Cc);
#pragma unroll
        for (int nt = 0; nt < 8; nt++) {
            mma8(c[0][nt], A0[0], B0[nt]);
            mma8(c[1][nt], A0[1], B0[nt]);
        }
        if (k0 + 64 < Cc) {
            ldA2(A0, abase, k0 + 64, Cc);
            ldB8(B0, bbase, k0 + 64, Cc);
        }
#pragma unroll
        for (int nt = 0; nt < 8; nt++) {
            mma8(c[0][nt], A1[0], B1[nt]);
            mma8(c[1][nt], A1[1], B1[nt]);
        }
    }

    const float c1 = __ldg(al_a) * __ldg(al_w);
    const float iq = c1 / __ldg(al_q), ik = c1 / __ldg(al_k), iv = c1 / __ldg(al_v);
#pragma unroll
    for (int mt = 0; mt < 2; mt++)
#pragma unroll
        for (int nt = 0; nt < 8; nt++)
#pragma unroll
            for (int j = 0; j < 4; j++) {
                int row = bm + wm + mt * 16 + lr + ((j >> 1) << 3);
                int col = bn + wn + nt * 8 + ((lane & 3) << 1) + (j & 1);
                float f = (float)c[mt][nt][j];
                int b = row >> 11, n = row & (Nn - 1);
                int which = col / Cc;
                int cr = col - which * Cc;
                int h = cr >> 6, d = cr & 63;
                if (which == 0)
                    g_q[((b * Hh + h) * Nn + n) * Dd + PHYS32(d)] = (int8_t)q8i(f * iq);
                else if (which == 1)
                    g_k[((b * Hh + h) * Nn + n) * Dd + PHYS32(d)] = (int8_t)q8i(f * ik);
                else
                    g_vT[((b * Hh + h) * Dd + d) * Nn + PHYS32(n)] = (int8_t)q8i(f * iv);
            }
}

// ---------------- fused attention: 128 threads, 3 CTAs/SM, prefetched operands ----
#define LUTF_OFF (32 * SROW)           // 66048: float[256] exp LUT
#define LUT8_OFF (LUTF_OFF + 1024)     // 67072: per-warp int8 requant LUT (4*256)
#define SUMS_OFF (LUT8_OFF + 1024)     // 68096: float[4][32] per-warp row partials
#define INVR_OFF (SUMS_OFF + 512)      // 68608: float[32] per-row inv
#define SMEM_SZ  (INVR_OFF + 128)      // 68736  (x3 CTAs = 206KB <= 228KB)

__device__ __forceinline__ void qk_ldK(unsigned b[4][2][2], const int8_t* kp, int col0) {
#pragma unroll
    for (int nt = 0; nt < 4; nt++)
#pragma unroll
        for (int ks = 0; ks < 2; ks++) {
            uint2 bv = *(const uint2*)(kp + (col0 + nt * 8) * Dd + ks * 32);
            b[nt][ks][0] = bv.x; b[nt][ks][1] = bv.y;
        }
}
__device__ __forceinline__ void qk_chunk(const unsigned a[2][2][4], const unsigned b[4][2][2],
                                         int col0, int lr, int lane, float c2i,
                                         const float* lutf, float* rsum, int8_t* s_s) {
    int c[2][4][4];
#pragma unroll
    for (int i = 0; i < 2; i++)
#pragma unroll
        for (int j = 0; j < 4; j++)
#pragma unroll
            for (int t = 0; t < 4; t++) c[i][j][t] = 0;
#pragma unroll
    for (int nt = 0; nt < 4; nt++)
#pragma unroll
        for (int ks = 0; ks < 2; ks++) {
            mma8(c[0][nt], a[0][ks], b[nt][ks]);
            mma8(c[1][nt], a[1][ks], b[nt][ks]);
        }
#pragma unroll
    for (int mt = 0; mt < 2; mt++)
#pragma unroll
        for (int nt = 0; nt < 4; nt++)
#pragma unroll
            for (int jj = 0; jj < 2; jj++) {
                int row = mt * 16 + lr + jj * 8;
                int col = col0 + nt * 8 + ((lane & 3) << 1);
                int pc = PHYS32(col);
                int v0 = q8i((float)c[mt][nt][jj * 2 + 0] * c2i);
                int v1 = q8i((float)c[mt][nt][jj * 2 + 1] * c2i);
                rsum[mt * 2 + jj] += lutf[v0 & 255] + lutf[v1 & 255];
                char2 o;
                o.x = (char)v0; o.y = (char)v1;
                *(char2*)(s_s + row * SROW + pc) = o;
            }
}
__device__ __forceinline__ void pv_ldV(unsigned v[4][2], const int8_t* vt, int k0) {
#pragma unroll
    for (int nt = 0; nt < 4; nt++) {
        uint2 bv = *(const uint2*)(vt + nt * 8 * Nn + k0);
        v[nt][0] = bv.x; v[nt][1] = bv.y;
    }
}

__global__ void __launch_bounds__(128, 3) attn_fused_k(
    const float* al_q, const float* al_k, const float* al_attn, const float* al_attn2,
    const float* al_v, const float* al_pa) {
    extern __shared__ int8_t s_s[];  // [32][SROW] scores/probs + LUTs + sums
    const int bh = blockIdx.y;
    const int rb = blockIdx.x * 32;
    const int8_t* qp = g_q + bh * Nn * Dd;
    const int tid = threadIdx.x;
    const int wid = tid >> 5;
    const int lane = tid & 31;
    const int lr = lane >> 2;
    const int q8 = (lane & 3) << 3;
    const float aAttn = __ldg(al_attn);
    const float c2i = __ldg(al_q) * __ldg(al_k) * 0.125f / aAttn;
    const float a2 = __ldg(al_attn2);
    const int8_t* kp = g_k + bh * Nn * Dd + lr * Dd + q8;

    // build float exp LUT: lutf[u] = exp2(k2 * (signed char)u)
    float* lutf = (float*)(s_s + LUTF_OFF);
    {
        const float k2 = aAttn * 1.44269504f;
        lutf[tid] = exp2f(k2 * (float)(char)tid);
        lutf[tid + 128] = exp2f(k2 * (float)(char)(tid + 128));
    }

    // preload q fragments for the 32 rows (2 m-tiles), K=64 (2 k-steps)
    unsigned a[2][2][4];
#pragma unroll
    for (int mt = 0; mt < 2; mt++)
#pragma unroll
        for (int ks = 0; ks < 2; ks++) {
            const int8_t* ap = qp + (rb + mt * 16 + lr) * Dd + ks * 32 + q8;
            uint2 lo = *(const uint2*)ap;
            uint2 hi = *(const uint2*)(ap + 8 * Dd);
            a[mt][ks][0] = lo.x; a[mt][ks][2] = lo.y;
            a[mt][ks][1] = hi.x; a[mt][ks][3] = hi.y;
        }
    __syncthreads();   // lutf ready before Phase A uses it

    // ---- Phase A: QK^T over 512-col stripe per warp, K-fragments double-buffered ----
    float rsum[4] = {0.f, 0.f, 0.f, 0.f};  // rows: lr, lr+8, 16+lr, 24+lr
    const int nbase = wid * 512;
    {
        unsigned B0[4][2][2], B1[4][2][2];
        qk_ldK(B0, kp, nbase);
#pragma unroll 1
        for (int nc = 0; nc < 512; nc += 64) {
            qk_ldK(B1, kp, nbase + nc + 32);
            qk_chunk(a, B0, nbase + nc, lr, lane, c2i, lutf, rsum, s_s);
            if (nc + 64 < 512) qk_ldK(B0, kp, nbase + nc + 64);
            qk_chunk(a, B1, nbase + nc + 32, lr, lane, c2i, lutf, rsum, s_s);
        }
    }
#pragma unroll
    for (int i = 0; i < 4; i++) {
        rsum[i] += __shfl_xor_sync(0xffffffffu, rsum[i], 1);
        rsum[i] += __shfl_xor_sync(0xffffffffu, rsum[i], 2);
    }
    if ((lane & 3) == 0) {
        float* sm = (float*)(s_s + SUMS_OFF) + wid * 32;
        sm[lr] = rsum[0]; sm[lr + 8] = rsum[1];
        sm[lr + 16] = rsum[2]; sm[lr + 24] = rsum[3];
    }
    __syncthreads();
    if (tid < 32) {
        const float* sm = (float*)(s_s + SUMS_OFF);
        float t = sm[tid] + sm[32 + tid] + sm[64 + tid] + sm[96 + tid];
        ((float*)(s_s + INVR_OFF))[tid] = 1.f / (t * a2);
    }
    __syncthreads();

    // ---- Phase B: per-row requant via per-warp int8 LUT (8 rows/warp) ----
    {
        int8_t* lut8w = s_s + LUT8_OFF + wid * 256;
        const float* invr = (const float*)(s_s + INVR_OFF);
#pragma unroll 1
        for (int r = wid * 8; r < wid * 8 + 8; r++) {
            int8_t* srow = s_s + r * SROW;
            const float inv = invr[r];
            unsigned lo = 0, hi = 0;
#pragma unroll
            for (int j = 0; j < 8; j++) {
                int m = __float2int_rn(fminf(lutf[lane * 8 + j] * inv, 127.f));
                if (j < 4) lo |= (unsigned)(m & 255) << (8 * j);
                else       hi |= (unsigned)(m & 255) << (8 * (j - 4));
            }
            *(uint2*)(lut8w + lane * 8) = make_uint2(lo, hi);
            __syncwarp();
#pragma unroll
            for (int it = 0; it < 16; it++) {
                int8_t* p = srow + lane * 4 + it * 128;
                unsigned w = *(const unsigned*)p;
                unsigned r0 = (unsigned char)lut8w[w & 255];
                unsigned r1 = (unsigned char)lut8w[(w >> 8) & 255];
                unsigned r2 = (unsigned char)lut8w[(w >> 16) & 255];
                unsigned r3 = (unsigned char)lut8w[w >> 24];
                *(unsigned*)p = r0 | (r1 << 8) | (r2 << 16) | (r3 << 24);
            }
            __syncwarp();
        }
    }
    __syncthreads();

    // ---- Phase C: out = P @ V; 16 rows x 32 cols per warp, V double-buffered ----
    {
        const int8_t* Vt = g_vT + bh * Dd * Nn;
        const int wm2 = (wid & 1) * 16;
        const int wn2 = (wid >> 1) * 32;
        const int8_t* vt0 = Vt + (wn2 + lr) * Nn + q8;
        const int8_t* ap0 = s_s + (wm2 + lr) * SROW + q8;
        int c[4][4];
#pragma unroll
        for (int i = 0; i < 4; i++)
#pragma unroll
            for (int t = 0; t < 4; t++) c[i][t] = 0;

        unsigned V0[4][2], V1[4][2];
        pv_ldV(V0, vt0, 0);
#pragma unroll 1
        for (int k0 = 0; k0 < Nn; k0 += 64) {
            pv_ldV(V1, vt0, k0 + 32);
            {
                unsigned af[4];
                const int8_t* ap = ap0 + k0;
                uint2 lo = *(const uint2*)ap;
                uint2 hi = *(const uint2*)(ap + 8 * SROW);
                af[0] = lo.x; af[2] = lo.y;
                af[1] = hi.x; af[3] = hi.y;
#pragma unroll
                for (int nt = 0; nt < 4; nt++) mma8(c[nt], af, V0[nt]);
            }
            if (k0 + 64 < Nn) pv_ldV(V0, vt0, k0 + 64);
            {
                unsigned af[4];
                const int8_t* ap = ap0 + k0 + 32;
                uint2 lo = *(const uint2*)ap;
                uint2 hi = *(const uint2*)(ap + 8 * SROW);
                af[0] = lo.x; af[2] = lo.y;
                af[1] = hi.x; af[3] = hi.y;
#pragma unroll
                for (int nt = 0; nt < 4; nt++) mma8(c[nt], af, V1[nt]);
            }
        }

        const float c3 = __ldg(al_attn2) * __ldg(al_v);
        const float ipa = c3 / __ldg(al_pa);
        const int b = bh / Hh, h = bh % Hh;
#pragma unroll
        for (int nt = 0; nt < 4; nt++)
#pragma unroll
            for (int j = 0; j < 4; j++) {
                int n = rb + wm2 + lr + ((j >> 1) << 3);
                int d = wn2 + nt * 8 + ((lane & 3) << 1) + (j & 1);
                g_o[(b * Nn + n) * Cc + h * Dd + PHYS32(d)] =
                    (int8_t)q8i((float)c[nt][j] * ipa);
            }
    }
}

// ---------------- GEMM2: 64x128 tile, A/B double-buffered ----------------
__global__ void __launch_bounds__(256) gemm_proj_k(
    float* __restrict__ out, const float* __restrict__ bias,
    const float* al_pa, const float* al_pw) {
    const int bm = blockIdx.y * 64;
    const int bn = blockIdx.x * 128;
    const int wid = threadIdx.x >> 5;
    const int lane = threadIdx.x & 31;
    const int wm = (wid & 3) * 16;
    const int wn = (wid >> 2) * 64;
    const int lr = lane >> 2;
    const int q8 = (lane & 3) << 3;
    const int8_t* abase = g_o + (bm + wm + lr) * Cc + q8;
    const int8_t* bbase = g_wproj + (bn + wn + lr) * Cc + q8;

    int c[8][4];
#pragma unroll
    for (int j = 0; j < 8; j++)
#pragma unroll
        for (int t = 0; t < 4; t++) c[j][t] = 0;

    unsigned A0[4], A1[4], B0[8][2], B1[8][2];
    {
        uint2 lo = *(const uint2*)abase;
        uint2 hi = *(const uint2*)(abase + 8 * Cc);
        A0[0] = lo.x; A0[2] = lo.y; A0[1] = hi.x; A0[3] = hi.y;
    }
    ldB8(B0, bbase, 0, Cc);
#pragma unroll 1
    for (int k0 = 0; k0 < Cc; k0 += 64) {
        {
            uint2 lo = *(const uint2*)(abase + k0 + 32);
            uint2 hi = *(const uint2*)(abase + k0 + 32 + 8 * Cc);
            A1[0] = lo.x; A1[2] = lo.y; A1[1] = hi.x; A1[3] = hi.y;
        }
        ldB8(B1, bbase, k0 + 32, Cc);
#pragma unroll
        for (int nt = 0; nt < 8; nt++) mma8(c[nt], A0, B0[nt]);
        if (k0 + 64 < Cc) {
            uint2 lo = *(const uint2*)(abase + k0 + 64);
            uint2 hi = *(const uint2*)(abase + k0 + 64 + 8 * Cc);
            A0[0] = lo.x; A0[2] = lo.y; A0[1] = hi.x; A0[3] = hi.y;
            ldB8(B0, bbase, k0 + 64, Cc);
        }
#pragma unroll
        for (int nt = 0; nt < 8; nt++) mma8(c[nt], A1, B1[nt]);
    }

    const float sc = __ldg(al_pa) * __ldg(al_pw);
#pragma unroll
    for (int nt = 0; nt < 8; nt++)
#pragma unroll
        for (int j = 0; j < 4; j++) {
            int row = bm + wm + lr + ((j >> 1) << 3);
            int col = bn + wn + nt * 8 + ((lane & 3) << 1) + (j & 1);
            out[row * Cc + col] = (float)c[nt][j] * sc + __ldg(bias + col);
        }
}

extern "C" void kernel_launch(void* const* d_in, const int* in_sizes, int n_in,
                              void* d_out, int out_size) {
    const float* x        = (const float*)d_in[0];
    const float* w_qkv    = (const float*)d_in[1];
    const float* w_proj   = (const float*)d_in[2];
    const float* b_proj   = (const float*)d_in[3];
    const float* a_qkv_w  = (const float*)d_in[4];
    const float* a_qkv_a  = (const float*)d_in[5];
    const float* a_proj_w = (const float*)d_in[6];
    const float* a_proj_a = (const float*)d_in[7];
    const float* a_q      = (const float*)d_in[8];
    const float* a_k      = (const float*)d_in[9];
    const float* a_v      = (const float*)d_in[10];
    const float* a_attn   = (const float*)d_in[11];
    const float* a_attn2  = (const float*)d_in[12];
    float* out = (float*)d_out;

    quant_all_k<<<2112, 256>>>(x, w_qkv, w_proj, a_qkv_a, a_qkv_w, a_proj_w);

    gemm_qkv_k<<<dim3(C3 / 128, BN / 128), 256>>>(a_qkv_a, a_qkv_w, a_q, a_k, a_v);

    cudaFuncSetAttribute(attn_fused_k, cudaFuncAttributeMaxDynamicSharedMemorySize, SMEM_SZ);
    attn_fused_k<<<dim3(Nn / 32, BHh), 128, SMEM_SZ>>>(a_q, a_k, a_attn, a_attn2, a_v, a_proj_a);

    gemm_proj_k<<<dim3(Cc / 128, BN / 64), 256>>>(out, b_proj, a_proj_a, a_proj_w);
}